// round 9
// baseline (speedup 1.0000x reference)
#include <cuda_runtime.h>
#include <cuda_fp16.h>

// Problem constants
#define NB 4
#define NQ 256
#define NK 1024
#define ND 512
#define NH 256

// GEMM tiling
#define BM 64
#define BN 64
#define BK 16
#define KSPLIT 4
#define KCHUNK (NK / KSPLIT)   // 256

__device__ __align__(16) float  g_qproj[NB * NQ * NH];   // [bq][h]
__device__ __align__(16) __half g_kTh[NB * NH * NK];     // [b][h][k] fp16
__device__ __align__(16) float  g_attn[NB * NQ * NK];    // [bq][k]
__device__ __align__(16) float  g_part[NB * KSPLIT * NQ * ND];  // split-K partials

__device__ __forceinline__ __half2 h2tanh_fast(__half2 a) {
    __half2 r;
    asm("tanh.approx.f16x2 %0, %1;"
        : "=r"(*reinterpret_cast<unsigned int*>(&r))
        : "r"(*reinterpret_cast<unsigned int*>(&a)));
    return r;
}

__device__ __forceinline__ float cvt_tf32(float x) {
    unsigned u;
    asm("cvt.rna.tf32.f32 %0, %1;" : "=r"(u) : "f"(x));
    return __uint_as_float(u);
}

__device__ __forceinline__ void mma_tf32(float c[4], const unsigned a[4],
                                         const unsigned b[2]) {
    asm volatile(
        "mma.sync.aligned.m16n8k8.row.col.f32.tf32.tf32.f32 "
        "{%0,%1,%2,%3}, {%4,%5,%6,%7}, {%8,%9}, {%0,%1,%2,%3};"
        : "+f"(c[0]), "+f"(c[1]), "+f"(c[2]), "+f"(c[3])
        : "r"(a[0]), "r"(a[1]), "r"(a[2]), "r"(a[3]), "r"(b[0]), "r"(b[1]));
}

// packed fp32x2 helpers (sm_103a FFMA2) — IEEE-identical to 2x fmaf
__device__ __forceinline__ unsigned long long pack_f32x2(float lo, float hi) {
    unsigned long long r;
    asm("mov.b64 %0, {%1, %2};" : "=l"(r) : "f"(lo), "f"(hi));
    return r;
}
__device__ __forceinline__ void unpack_f32x2(unsigned long long v, float& lo, float& hi) {
    asm("mov.b64 {%0, %1}, %2;" : "=f"(lo), "=f"(hi) : "l"(v));
}
__device__ __forceinline__ void fma_f32x2(unsigned long long& acc,
                                          unsigned long long a, unsigned long long b) {
    asm("fma.rn.f32x2 %0, %1, %2, %0;" : "+l"(acc) : "l"(a), "l"(b));
}

// ---------------------------------------------------------------------------
// smem helpers (k-major [BK][64+4])
// ---------------------------------------------------------------------------
__device__ __forceinline__ void stsT_tf32(float S[BK][BM + 4], float4 v, int lk, int row) {
    S[lk + 0][row] = cvt_tf32(v.x);
    S[lk + 1][row] = cvt_tf32(v.y);
    S[lk + 2][row] = cvt_tf32(v.z);
    S[lk + 3][row] = cvt_tf32(v.w);
}

__device__ __forceinline__ float4 cvt4_tf32(float4 v) {
    return make_float4(cvt_tf32(v.x), cvt_tf32(v.y), cvt_tf32(v.z), cvt_tf32(v.w));
}

// tf32 mma over one BK=16 slab; warp tile 32x32 (2 m16 x 4 n8 x 2 k8)
__device__ __forceinline__ void mma_slab(const float As[BK][BM + 4],
                                         const float Bs[BK][BN + 4],
                                         float acc[2][4][4], int wr, int wc, int lane) {
    const int qk = lane & 3, qr = lane >> 2;
#pragma unroll
    for (int ks = 0; ks < BK; ks += 8) {
        unsigned a[2][4], b[4][2];
#pragma unroll
        for (int mt = 0; mt < 2; mt++) {
            const int r = wr + mt * 16 + qr;
            a[mt][0] = __float_as_uint(As[ks + qk][r]);
            a[mt][1] = __float_as_uint(As[ks + qk][r + 8]);
            a[mt][2] = __float_as_uint(As[ks + 4 + qk][r]);
            a[mt][3] = __float_as_uint(As[ks + 4 + qk][r + 8]);
        }
#pragma unroll
        for (int nt = 0; nt < 4; nt++) {
            const int n = wc + nt * 8 + qr;
            b[nt][0] = __float_as_uint(Bs[ks + qk][n]);
            b[nt][1] = __float_as_uint(Bs[ks + 4 + qk][n]);
        }
#pragma unroll
        for (int mt = 0; mt < 2; mt++)
#pragma unroll
            for (int nt = 0; nt < 4; nt++)
                mma_tf32(acc[mt][nt], a[mt], b[nt]);
    }
}

// ---------------------------------------------------------------------------
// q/k projection (NT GEMMs) via tf32 tensor cores, one kernel, two launches.
//  mode 0: qproj  C[bq][h]    = queries(1024x512) @ Wq(256x512)^T  (fp32 out)
//  mode 1: kproj  kTh[b][h][k] = Wk(256x512) @ keys(4096x512)^T    (fp16 out)
// ---------------------------------------------------------------------------
__global__ void __launch_bounds__(128) proj_gemm(const float* __restrict__ Ain,
                                                 const float* __restrict__ Win,
                                                 const int* __restrict__ vlen,
                                                 int mode) {
    __shared__ __align__(16) float As[BK][BM + 4];
    __shared__ __align__(16) float Bs[BK][BN + 4];
    const int K = 512;
    const int bid = blockIdx.x, tid = threadIdx.x;

    const float *A, *B;
    int m0, n0;
    if (mode == 0) {
        m0 = (bid >> 2) * BM;  // 16 m-tiles over 1024 query rows
        n0 = (bid & 3) * BN;   // 4 n-tiles over 256 h
        A = Ain; B = Win;
    } else {
        m0 = (bid >> 6) * BM;  // 4 m-tiles over 256 h
        n0 = (bid & 63) * BN;  // 64 n-tiles over 4096 (b,k)
        // dead k-tile: no consumer ever reads kT for k >= vlen[b]
        if ((n0 & 1023) >= vlen[n0 >> 10]) return;
        A = Win; B = Ain;
    }

    const int lr = tid >> 2;
    const int lk = (tid & 3) << 2;
    const float* Ap = A + (size_t)(m0 + lr) * K + lk;
    const float* Bp = B + (size_t)(n0 + lr) * K + lk;

    float4 a0 = *(const float4*)Ap;
    float4 a1 = *(const float4*)(Ap + 32 * K);
    float4 b0 = *(const float4*)Bp;
    float4 b1 = *(const float4*)(Bp + 32 * K);
    stsT_tf32(As, a0, lk, lr); stsT_tf32(As, a1, lk, lr + 32);
    stsT_tf32(Bs, b0, lk, lr); stsT_tf32(Bs, b1, lk, lr + 32);
    __syncthreads();

    float acc[2][4][4] = {};
    const int lane = tid & 31, wid = tid >> 5;
    const int wr = (wid & 1) * 32, wc = (wid >> 1) * 32;

    for (int k0 = BK; k0 < K; k0 += BK) {
        a0 = *(const float4*)(Ap + k0);
        a1 = *(const float4*)(Ap + 32 * K + k0);
        b0 = *(const float4*)(Bp + k0);
        b1 = *(const float4*)(Bp + 32 * K + k0);
        mma_slab(As, Bs, acc, wr, wc, lane);
        __syncthreads();
        stsT_tf32(As, a0, lk, lr); stsT_tf32(As, a1, lk, lr + 32);
        stsT_tf32(Bs, b0, lk, lr); stsT_tf32(Bs, b1, lk, lr + 32);
        __syncthreads();
    }
    mma_slab(As, Bs, acc, wr, wc, lane);

#pragma unroll
    for (int mt = 0; mt < 2; mt++) {
#pragma unroll
        for (int nt = 0; nt < 4; nt++) {
            const int r0 = m0 + wr + mt * 16 + (lane >> 2);
            const int cn = wc + nt * 8 + 2 * (lane & 3);
            if (mode == 0) {
                *(float2*)&g_qproj[(size_t)r0 * NH + n0 + cn] =
                    make_float2(acc[mt][nt][0], acc[mt][nt][1]);
                *(float2*)&g_qproj[(size_t)(r0 + 8) * NH + n0 + cn] =
                    make_float2(acc[mt][nt][2], acc[mt][nt][3]);
            } else {
                // fp16 store — same __float2half_rn rounding scores used to do
                const int gb = n0 >> 10;
                const int kx = (n0 & 1023) + cn;
                *(__half2*)&g_kTh[(size_t)(gb * NH + r0) * NK + kx] =
                    __floats2half2_rn(acc[mt][nt][0], acc[mt][nt][1]);
                *(__half2*)&g_kTh[(size_t)(gb * NH + r0 + 8) * NK + kx] =
                    __floats2half2_rn(acc[mt][nt][2], acc[mt][nt][3]);
            }
        }
    }
}

// ---------------------------------------------------------------------------
// Scores + masked softmax. 128 blocks, 512 threads.
// k loaded as fp16 (one LDG.32 / iter), packed FFMA2 fp32 accumulation.
// ---------------------------------------------------------------------------
__global__ void __launch_bounds__(512) scores_kernel(const int* __restrict__ vlen,
                                                     const float* __restrict__ wv) {
    __shared__ float qsT[NH][8];
    __shared__ __half2 qsh[NH][4];
    __shared__ float wvs[NH];
    __shared__ float wred[16][8];
    __shared__ float bred[8];

    const int tid = threadIdx.x;
    const int b = blockIdx.x >> 5;
    const int q0 = (blockIdx.x & 31) << 3;
    const int vl = vlen[b];
    const int kb2 = tid * 2;

    if (tid < NH) wvs[tid] = wv[tid];
#pragma unroll
    for (int i = 0; i < 4; i++) {
        const int idx = tid + i * 512;
        const int h = idx >> 3, r = idx & 7;
        qsT[h][r] = g_qproj[(size_t)(b * NQ + q0 + r) * NH + h];
    }
    __syncthreads();
#pragma unroll
    for (int i = 0; i < 2; i++) {
        const int idx = tid + i * 512;
        const int h = idx >> 2, rp = idx & 3;
        qsh[h][rp] = __floats2half2_rn(qsT[h][2 * rp], qsT[h][2 * rp + 1]);
    }
    __syncthreads();

    // acc2[rp][j]: packed (row 2rp, row 2rp+1) accumulator for key j
    unsigned long long acc2[4][2] = {};
    if (kb2 < vl) {   // fully-masked threads skip all loads + tanh work (exact)
        const __half2* kp = (const __half2*)g_kTh + (size_t)b * NH * (NK / 2) + tid;
#pragma unroll 4
        for (int h = 0; h < NH; h++) {
            const __half2 kv2 = kp[h * (NK / 2)];        // keys 2t, 2t+1 (fp16)
            const __half2 k0 = __low2half2(kv2);
            const __half2 k1 = __high2half2(kv2);
            const float w = wvs[h];
            const unsigned long long w2 = pack_f32x2(w, w);
#pragma unroll
            for (int rp = 0; rp < 4; rp++) {
                const __half2 q2 = qsh[h][rp];
                const float2 f0 = __half22float2(h2tanh_fast(__hadd2(q2, k0)));
                const float2 f1 = __half22float2(h2tanh_fast(__hadd2(q2, k1)));
                fma_f32x2(acc2[rp][0], w2, pack_f32x2(f0.x, f0.y));
                fma_f32x2(acc2[rp][1], w2, pack_f32x2(f1.x, f1.y));
            }
        }
    }

    float acc[8][2];
#pragma unroll
    for (int rp = 0; rp < 4; rp++) {
        unpack_f32x2(acc2[rp][0], acc[2 * rp][0], acc[2 * rp + 1][0]);
        unpack_f32x2(acc2[rp][1], acc[2 * rp][1], acc[2 * rp + 1][1]);
    }

    float s0[8], s1[8], rm[8];
#pragma unroll
    for (int r = 0; r < 8; r++) {
        s0[r] = (kb2 < vl) ? acc[r][0] : -1e6f;
        s1[r] = (kb2 + 1 < vl) ? acc[r][1] : -1e6f;
        rm[r] = fmaxf(s0[r], s1[r]);
    }
#pragma unroll
    for (int o = 16; o > 0; o >>= 1)
#pragma unroll
        for (int r = 0; r < 8; r++)
            rm[r] = fmaxf(rm[r], __shfl_xor_sync(0xffffffffu, rm[r], o));
    const int wid = tid >> 5, lane = tid & 31;
    if (lane == 0)
#pragma unroll
        for (int r = 0; r < 8; r++) wred[wid][r] = rm[r];
    __syncthreads();
    if (tid < 8) {
        float m = wred[0][tid];
#pragma unroll
        for (int w2 = 1; w2 < 16; w2++) m = fmaxf(m, wred[w2][tid]);
        bred[tid] = m;
    }
    __syncthreads();

    float e0[8], e1[8], rs[8];
#pragma unroll
    for (int r = 0; r < 8; r++) {
        const float mx = bred[r];
        e0[r] = __expf(s0[r] - mx);
        e1[r] = __expf(s1[r] - mx);
        rs[r] = e0[r] + e1[r];
    }
#pragma unroll
    for (int o = 16; o > 0; o >>= 1)
#pragma unroll
        for (int r = 0; r < 8; r++)
            rs[r] += __shfl_xor_sync(0xffffffffu, rs[r], o);
    if (lane == 0)
#pragma unroll
        for (int r = 0; r < 8; r++) wred[wid][r] = rs[r];
    __syncthreads();
    if (tid < 8) {
        float s = 0.0f;
#pragma unroll
        for (int w2 = 0; w2 < 16; w2++) s += wred[w2][tid];
        bred[tid] = 1.0f / s;
    }
    __syncthreads();

    // av only reads attn for k < ceil(vl/KCHUNK)*KCHUNK — skip dead stores
    const int klim = ((vl + KCHUNK - 1) / KCHUNK) * KCHUNK;
    if (kb2 < klim) {
#pragma unroll
        for (int r = 0; r < 8; r++) {
            const float inv = bred[r];
            float2 o2 = make_float2(e0[r] * inv, e1[r] * inv);
            *reinterpret_cast<float2*>(&g_attn[(size_t)(b * NQ + q0 + r) * NK + kb2]) = o2;
        }
    }
}

// ---------------------------------------------------------------------------
// Split-K attn @ values via tf32 tensor cores; partials to g_part.
// Inactive chunks exit immediately; reduce_kernel only reads active splits.
// ---------------------------------------------------------------------------
__global__ void __launch_bounds__(128) av_gemm(const float* __restrict__ V,
                                               const int* __restrict__ vlen) {
    __shared__ __align__(16) float As[BK][BM + 4];
    __shared__ __align__(16) float Bs[BK][BN + 4];
    const int tid = threadIdx.x;
    const int b = blockIdx.z >> 2;
    const int split = blockIdx.z & 3;
    const int kbase = split * KCHUNK;
    if (kbase >= vlen[b]) return;   // partial is exactly zero; reduce skips it
    const int m0 = blockIdx.y * BM;
    const int n0 = blockIdx.x * BN;

    float acc[2][4][4] = {};
    const int lane = tid & 31, wid = tid >> 5;
    const int wr = (wid & 1) * 32, wc = (wid >> 1) * 32;

    const float* A = g_attn + (size_t)b * NQ * NK;
    const float* B = V + (size_t)b * NK * ND;

    const int lr = tid >> 2, lk = (tid & 3) << 2;   // A (transpose) loader
    const int bk = tid >> 4, bn = (tid & 15) << 2;  // B (direct) loader
    const float* Ap = A + (size_t)(m0 + lr) * NK + lk;
    const float* Bp = B + (size_t)bk * ND + n0 + bn;

    float4 a0 = *(const float4*)(Ap + kbase);
    float4 a1 = *(const float4*)(Ap + 32 * NK + kbase);
    float4 b0 = *(const float4*)(Bp + (size_t)kbase * ND);
    float4 b1 = *(const float4*)(Bp + (size_t)(kbase + 8) * ND);
    stsT_tf32(As, a0, lk, lr); stsT_tf32(As, a1, lk, lr + 32);
    *(float4*)&Bs[bk][bn] = cvt4_tf32(b0);
    *(float4*)&Bs[bk + 8][bn] = cvt4_tf32(b1);
    __syncthreads();

    for (int k0 = kbase + BK; k0 < kbase + KCHUNK; k0 += BK) {
        a0 = *(const float4*)(Ap + k0);
        a1 = *(const float4*)(Ap + 32 * NK + k0);
        b0 = *(const float4*)(Bp + (size_t)k0 * ND);
        b1 = *(const float4*)(Bp + (size_t)(k0 + 8) * ND);
        mma_slab(As, Bs, acc, wr, wc, lane);
        __syncthreads();
        stsT_tf32(As, a0, lk, lr); stsT_tf32(As, a1, lk, lr + 32);
        *(float4*)&Bs[bk][bn] = cvt4_tf32(b0);
        *(float4*)&Bs[bk + 8][bn] = cvt4_tf32(b1);
        __syncthreads();
    }
    mma_slab(As, Bs, acc, wr, wc, lane);

    float* P = g_part + (size_t)(b * KSPLIT + split) * NQ * ND;
#pragma unroll
    for (int mt = 0; mt < 2; mt++) {
#pragma unroll
        for (int nt = 0; nt < 4; nt++) {
            const int r0 = m0 + wr + mt * 16 + (lane >> 2);
            const int cn = n0 + wc + nt * 8 + 2 * (lane & 3);
            *(float2*)&P[(size_t)r0 * ND + cn] = make_float2(acc[mt][nt][0], acc[mt][nt][1]);
            *(float2*)&P[(size_t)(r0 + 8) * ND + cn] = make_float2(acc[mt][nt][2], acc[mt][nt][3]);
        }
    }
}

__global__ void __launch_bounds__(256) reduce_kernel(float* __restrict__ out,
                                                     const int* __restrict__ vlen) {
    const int i = blockIdx.x * 256 + threadIdx.x;   // float4 index, 131072 total
    const int b = i >> 15;
    const int off = i & 32767;
    const int nact = (vlen[b] + KCHUNK - 1) / KCHUNK;   // 1..KSPLIT active splits
    const float4* p = (const float4*)g_part;
    float4 s = p[(size_t)(b * KSPLIT + 0) * 32768 + off];
    for (int sp = 1; sp < nact; sp++) {
        const float4 t = p[(size_t)(b * KSPLIT + sp) * 32768 + off];
        s.x += t.x; s.y += t.y; s.z += t.z; s.w += t.w;
    }
    ((float4*)out)[i] = s;
}

// ---------------------------------------------------------------------------
extern "C" void kernel_launch(void* const* d_in, const int* in_sizes, int n_in,
                              void* d_out, int out_size) {
    const float* queries    = (const float*)d_in[0];
    const float* keys       = (const float*)d_in[1];
    const float* values     = (const float*)d_in[2];
    const int*   valid_lens = (const int*)d_in[3];
    const float* Wq         = (const float*)d_in[4];
    const float* Wk         = (const float*)d_in[5];
    const float* wv         = (const float*)d_in[6];
    float* out = (float*)d_out;

    (void)in_sizes; (void)n_in; (void)out_size;

    proj_gemm<<<64, 128>>>(queries, Wq, valid_lens, 0);    // launch 0: qproj
    proj_gemm<<<256, 128>>>(keys, Wk, valid_lens, 1);      // launch 1: kproj
    scores_kernel<<<128, 512>>>(valid_lens, wv);           // launch 2
    av_gemm<<<dim3(ND / BN, NQ / BM, NB * KSPLIT), 128>>>(values, valid_lens);  // launch 3 (profiled)
    reduce_kernel<<<512, 256>>>(out, valid_lens);          // launch 4
}

// round 10
// speedup vs baseline: 1.1721x; 1.1721x over previous
#include <cuda_runtime.h>
#include <cuda_fp16.h>

// Problem constants
#define NB 4
#define NQ 256
#define NK 1024
#define ND 512
#define NH 256

// GEMM tiling
#define BM 64
#define BN 64
#define BK 16
#define KSPLIT 4
#define KCHUNK (NK / KSPLIT)   // 256

__device__ __align__(16) float  g_qproj[NB * NQ * NH];   // [bq][h]
__device__ __align__(16) __half g_kTh[NB * NH * NK];     // [b][h][k] fp16
__device__ __align__(16) float  g_attn[NB * NQ * NK];    // [bq][k]
__device__ __align__(16) float  g_part[NB * KSPLIT * NQ * ND];  // split-K partials
__device__ float g_spacer_sink[32];

__device__ __forceinline__ __half2 h2tanh_fast(__half2 a) {
    __half2 r;
    asm("tanh.approx.f16x2 %0, %1;"
        : "=r"(*reinterpret_cast<unsigned int*>(&r))
        : "r"(*reinterpret_cast<unsigned int*>(&a)));
    return r;
}

__device__ __forceinline__ float cvt_tf32(float x) {
    unsigned u;
    asm("cvt.rna.tf32.f32 %0, %1;" : "=r"(u) : "f"(x));
    return __uint_as_float(u);
}

__device__ __forceinline__ void mma_tf32(float c[4], const unsigned a[4],
                                         const unsigned b[2]) {
    asm volatile(
        "mma.sync.aligned.m16n8k8.row.col.f32.tf32.tf32.f32 "
        "{%0,%1,%2,%3}, {%4,%5,%6,%7}, {%8,%9}, {%0,%1,%2,%3};"
        : "+f"(c[0]), "+f"(c[1]), "+f"(c[2]), "+f"(c[3])
        : "r"(a[0]), "r"(a[1]), "r"(a[2]), "r"(a[3]), "r"(b[0]), "r"(b[1]));
}

// packed fp32x2 helpers (sm_103a)
__device__ __forceinline__ unsigned long long pack_f32x2(float lo, float hi) {
    unsigned long long r;
    asm("mov.b64 %0, {%1, %2};" : "=l"(r) : "f"(lo), "f"(hi));
    return r;
}
__device__ __forceinline__ void unpack_f32x2(unsigned long long v, float& lo, float& hi) {
    asm("mov.b64 {%0, %1}, %2;" : "=f"(lo), "=f"(hi) : "l"(v));
}
__device__ __forceinline__ unsigned long long add_f32x2(unsigned long long a,
                                                        unsigned long long b) {
    unsigned long long r;
    asm("add.rn.f32x2 %0, %1, %2;" : "=l"(r) : "l"(a), "l"(b));
    return r;
}

// ---------------------------------------------------------------------------
// smem helpers (k-major [BK][64+4])
// ---------------------------------------------------------------------------
__device__ __forceinline__ void stsT_tf32(float S[BK][BM + 4], float4 v, int lk, int row) {
    S[lk + 0][row] = cvt_tf32(v.x);
    S[lk + 1][row] = cvt_tf32(v.y);
    S[lk + 2][row] = cvt_tf32(v.z);
    S[lk + 3][row] = cvt_tf32(v.w);
}

__device__ __forceinline__ float4 cvt4_tf32(float4 v) {
    return make_float4(cvt_tf32(v.x), cvt_tf32(v.y), cvt_tf32(v.z), cvt_tf32(v.w));
}

// tf32 mma over one BK=16 slab; warp tile 32x32 (2 m16 x 4 n8 x 2 k8)
__device__ __forceinline__ void mma_slab(const float As[BK][BM + 4],
                                         const float Bs[BK][BN + 4],
                                         float acc[2][4][4], int wr, int wc, int lane) {
    const int qk = lane & 3, qr = lane >> 2;
#pragma unroll
    for (int ks = 0; ks < BK; ks += 8) {
        unsigned a[2][4], b[4][2];
#pragma unroll
        for (int mt = 0; mt < 2; mt++) {
            const int r = wr + mt * 16 + qr;
            a[mt][0] = __float_as_uint(As[ks + qk][r]);
            a[mt][1] = __float_as_uint(As[ks + qk][r + 8]);
            a[mt][2] = __float_as_uint(As[ks + 4 + qk][r]);
            a[mt][3] = __float_as_uint(As[ks + 4 + qk][r + 8]);
        }
#pragma unroll
        for (int nt = 0; nt < 4; nt++) {
            const int n = wc + nt * 8 + qr;
            b[nt][0] = __float_as_uint(Bs[ks + qk][n]);
            b[nt][1] = __float_as_uint(Bs[ks + 4 + qk][n]);
        }
#pragma unroll
        for (int mt = 0; mt < 2; mt++)
#pragma unroll
            for (int nt = 0; nt < 4; nt++)
                mma_tf32(acc[mt][nt], a[mt], b[nt]);
    }
}

// ---------------------------------------------------------------------------
// q/k projection (NT GEMMs) via tf32 tensor cores, one kernel, two launches.
// ---------------------------------------------------------------------------
__global__ void __launch_bounds__(128) proj_gemm(const float* __restrict__ Ain,
                                                 const float* __restrict__ Win,
                                                 const int* __restrict__ vlen,
                                                 int mode) {
    __shared__ __align__(16) float As[BK][BM + 4];
    __shared__ __align__(16) float Bs[BK][BN + 4];
    const int K = 512;
    const int bid = blockIdx.x, tid = threadIdx.x;

    const float *A, *B;
    int m0, n0;
    if (mode == 0) {
        m0 = (bid >> 2) * BM;  // 16 m-tiles over 1024 query rows
        n0 = (bid & 3) * BN;   // 4 n-tiles over 256 h
        A = Ain; B = Win;
    } else {
        m0 = (bid >> 6) * BM;  // 4 m-tiles over 256 h
        n0 = (bid & 63) * BN;  // 64 n-tiles over 4096 (b,k)
        if ((n0 & 1023) >= vlen[n0 >> 10]) return;   // dead k-tile
        A = Win; B = Ain;
    }

    const int lr = tid >> 2;
    const int lk = (tid & 3) << 2;
    const float* Ap = A + (size_t)(m0 + lr) * K + lk;
    const float* Bp = B + (size_t)(n0 + lr) * K + lk;

    float4 a0 = *(const float4*)Ap;
    float4 a1 = *(const float4*)(Ap + 32 * K);
    float4 b0 = *(const float4*)Bp;
    float4 b1 = *(const float4*)(Bp + 32 * K);
    stsT_tf32(As, a0, lk, lr); stsT_tf32(As, a1, lk, lr + 32);
    stsT_tf32(Bs, b0, lk, lr); stsT_tf32(Bs, b1, lk, lr + 32);
    __syncthreads();

    float acc[2][4][4] = {};
    const int lane = tid & 31, wid = tid >> 5;
    const int wr = (wid & 1) * 32, wc = (wid >> 1) * 32;

    for (int k0 = BK; k0 < K; k0 += BK) {
        a0 = *(const float4*)(Ap + k0);
        a1 = *(const float4*)(Ap + 32 * K + k0);
        b0 = *(const float4*)(Bp + k0);
        b1 = *(const float4*)(Bp + 32 * K + k0);
        mma_slab(As, Bs, acc, wr, wc, lane);
        __syncthreads();
        stsT_tf32(As, a0, lk, lr); stsT_tf32(As, a1, lk, lr + 32);
        stsT_tf32(Bs, b0, lk, lr); stsT_tf32(Bs, b1, lk, lr + 32);
        __syncthreads();
    }
    mma_slab(As, Bs, acc, wr, wc, lane);

#pragma unroll
    for (int mt = 0; mt < 2; mt++) {
#pragma unroll
        for (int nt = 0; nt < 4; nt++) {
            const int r0 = m0 + wr + mt * 16 + (lane >> 2);
            const int cn = wc + nt * 8 + 2 * (lane & 3);
            if (mode == 0) {
                *(float2*)&g_qproj[(size_t)r0 * NH + n0 + cn] =
                    make_float2(acc[mt][nt][0], acc[mt][nt][1]);
                *(float2*)&g_qproj[(size_t)(r0 + 8) * NH + n0 + cn] =
                    make_float2(acc[mt][nt][2], acc[mt][nt][3]);
            } else {
                const int gb = n0 >> 10;
                const int kx = (n0 & 1023) + cn;
                *(__half2*)&g_kTh[(size_t)(gb * NH + r0) * NK + kx] =
                    __floats2half2_rn(acc[mt][nt][0], acc[mt][nt][1]);
                *(__half2*)&g_kTh[(size_t)(gb * NH + r0 + 8) * NK + kx] =
                    __floats2half2_rn(acc[mt][nt][2], acc[mt][nt][3]);
            }
        }
    }
}

// Spacer: pushes scores_kernel to launch index 3 so ncu's capture lands on it.
__global__ void spacer_kernel() {
    if (threadIdx.x < 32) g_spacer_sink[threadIdx.x] = 1.0f;
}

// ---------------------------------------------------------------------------
// Scores + masked softmax. 128 blocks, 512 threads.
// Hot loop: HFMA2 fp16 accumulation (8-step chunks) folded into packed f32 —
// no per-iteration f16->f32 conversions.
// ---------------------------------------------------------------------------
__global__ void __launch_bounds__(512) scores_kernel(const int* __restrict__ vlen,
                                                     const float* __restrict__ wv) {
    __shared__ float qsT[NH][8];
    __shared__ __half2 qsh[NH][4];
    __shared__ __half2 wvh[NH];
    __shared__ float wred[16][8];
    __shared__ float bred[8];

    const int tid = threadIdx.x;
    const int b = blockIdx.x >> 5;
    const int q0 = (blockIdx.x & 31) << 3;
    const int vl = vlen[b];
    const int kb2 = tid * 2;

    if (tid < NH) wvh[tid] = __float2half2_rn(wv[tid]);
#pragma unroll
    for (int i = 0; i < 4; i++) {
        const int idx = tid + i * 512;
        const int h = idx >> 3, r = idx & 7;
        qsT[h][r] = g_qproj[(size_t)(b * NQ + q0 + r) * NH + h];
    }
    __syncthreads();
#pragma unroll
    for (int i = 0; i < 2; i++) {
        const int idx = tid + i * 512;
        const int h = idx >> 2, rp = idx & 3;
        qsh[h][rp] = __floats2half2_rn(qsT[h][2 * rp], qsT[h][2 * rp + 1]);
    }
    __syncthreads();

    // packed f32 accumulators: accf[rp][j] = (row 2rp, row 2rp+1) for key j
    unsigned long long accf[4][2] = {};
    if (kb2 < vl) {   // fully-masked threads skip all loads + tanh work (exact)
        const __half2* kp = (const __half2*)g_kTh + (size_t)b * NH * (NK / 2) + tid;
        const __half2 hz = __float2half2_rn(0.0f);
#pragma unroll 1
        for (int hc = 0; hc < NH; hc += 8) {
            __half2 acch[4][2];
#pragma unroll
            for (int rp = 0; rp < 4; rp++) { acch[rp][0] = hz; acch[rp][1] = hz; }
#pragma unroll
            for (int hh = 0; hh < 8; hh++) {
                const int h = hc + hh;
                const __half2 kv2 = kp[(size_t)h * (NK / 2)];   // keys 2t, 2t+1
                const __half2 k0 = __low2half2(kv2);
                const __half2 k1 = __high2half2(kv2);
                const __half2 w2 = wvh[h];
#pragma unroll
                for (int rp = 0; rp < 4; rp++) {
                    const __half2 q2 = qsh[h][rp];
                    acch[rp][0] = __hfma2(w2, h2tanh_fast(__hadd2(q2, k0)), acch[rp][0]);
                    acch[rp][1] = __hfma2(w2, h2tanh_fast(__hadd2(q2, k1)), acch[rp][1]);
                }
            }
            // fold fp16 chunk into packed f32 accumulators
#pragma unroll
            for (int rp = 0; rp < 4; rp++) {
                const float2 f0 = __half22float2(acch[rp][0]);
                const float2 f1 = __half22float2(acch[rp][1]);
                accf[rp][0] = add_f32x2(accf[rp][0], pack_f32x2(f0.x, f0.y));
                accf[rp][1] = add_f32x2(accf[rp][1], pack_f32x2(f1.x, f1.y));
            }
        }
    }

    float acc[8][2];
#pragma unroll
    for (int rp = 0; rp < 4; rp++) {
        unpack_f32x2(accf[rp][0], acc[2 * rp][0], acc[2 * rp + 1][0]);
        unpack_f32x2(accf[rp][1], acc[2 * rp][1], acc[2 * rp + 1][1]);
    }

    float s0[8], s1[8], rm[8];
#pragma unroll
    for (int r = 0; r < 8; r++) {
        s0[r] = (kb2 < vl) ? acc[r][0] : -1e6f;
        s1[r] = (kb2 + 1 < vl) ? acc[r][1] : -1e6f;
        rm[r] = fmaxf(s0[r], s1[r]);
    }
#pragma unroll
    for (int o = 16; o > 0; o >>= 1)
#pragma unroll
        for (int r = 0; r < 8; r++)
            rm[r] = fmaxf(rm[r], __shfl_xor_sync(0xffffffffu, rm[r], o));
    const int wid = tid >> 5, lane = tid & 31;
    if (lane == 0)
#pragma unroll
        for (int r = 0; r < 8; r++) wred[wid][r] = rm[r];
    __syncthreads();
    if (tid < 8) {
        float m = wred[0][tid];
#pragma unroll
        for (int w2 = 1; w2 < 16; w2++) m = fmaxf(m, wred[w2][tid]);
        bred[tid] = m;
    }
    __syncthreads();

    float e0[8], e1[8], rs[8];
#pragma unroll
    for (int r = 0; r < 8; r++) {
        const float mx = bred[r];
        e0[r] = __expf(s0[r] - mx);
        e1[r] = __expf(s1[r] - mx);
        rs[r] = e0[r] + e1[r];
    }
#pragma unroll
    for (int o = 16; o > 0; o >>= 1)
#pragma unroll
        for (int r = 0; r < 8; r++)
            rs[r] += __shfl_xor_sync(0xffffffffu, rs[r], o);
    if (lane == 0)
#pragma unroll
        for (int r = 0; r < 8; r++) wred[wid][r] = rs[r];
    __syncthreads();
    if (tid < 8) {
        float s = 0.0f;
#pragma unroll
        for (int w2 = 0; w2 < 16; w2++) s += wred[w2][tid];
        bred[tid] = 1.0f / s;
    }
    __syncthreads();

    // av only reads attn for k < ceil(vl/KCHUNK)*KCHUNK — skip dead stores
    const int klim = ((vl + KCHUNK - 1) / KCHUNK) * KCHUNK;
    if (kb2 < klim) {
#pragma unroll
        for (int r = 0; r < 8; r++) {
            const float inv = bred[r];
            float2 o2 = make_float2(e0[r] * inv, e1[r] * inv);
            *reinterpret_cast<float2*>(&g_attn[(size_t)(b * NQ + q0 + r) * NK + kb2]) = o2;
        }
    }
}

// ---------------------------------------------------------------------------
// Split-K attn @ values via tf32 tensor cores; partials to g_part.
// ---------------------------------------------------------------------------
__global__ void __launch_bounds__(128) av_gemm(const float* __restrict__ V,
                                               const int* __restrict__ vlen) {
    __shared__ __align__(16) float As[BK][BM + 4];
    __shared__ __align__(16) float Bs[BK][BN + 4];
    const int tid = threadIdx.x;
    const int b = blockIdx.z >> 2;
    const int split = blockIdx.z & 3;
    const int kbase = split * KCHUNK;
    if (kbase >= vlen[b]) return;   // partial is exactly zero; reduce skips it
    const int m0 = blockIdx.y * BM;
    const int n0 = blockIdx.x * BN;

    float acc[2][4][4] = {};
    const int lane = tid & 31, wid = tid >> 5;
    const int wr = (wid & 1) * 32, wc = (wid >> 1) * 32;

    const float* A = g_attn + (size_t)b * NQ * NK;
    const float* B = V + (size_t)b * NK * ND;

    const int lr = tid >> 2, lk = (tid & 3) << 2;   // A (transpose) loader
    const int bk = tid >> 4, bn = (tid & 15) << 2;  // B (direct) loader
    const float* Ap = A + (size_t)(m0 + lr) * NK + lk;
    const float* Bp = B + (size_t)bk * ND + n0 + bn;

    float4 a0 = *(const float4*)(Ap + kbase);
    float4 a1 = *(const float4*)(Ap + 32 * NK + kbase);
    float4 b0 = *(const float4*)(Bp + (size_t)kbase * ND);
    float4 b1 = *(const float4*)(Bp + (size_t)(kbase + 8) * ND);
    stsT_tf32(As, a0, lk, lr); stsT_tf32(As, a1, lk, lr + 32);
    *(float4*)&Bs[bk][bn] = cvt4_tf32(b0);
    *(float4*)&Bs[bk + 8][bn] = cvt4_tf32(b1);
    __syncthreads();

    for (int k0 = kbase + BK; k0 < kbase + KCHUNK; k0 += BK) {
        a0 = *(const float4*)(Ap + k0);
        a1 = *(const float4*)(Ap + 32 * NK + k0);
        b0 = *(const float4*)(Bp + (size_t)k0 * ND);
        b1 = *(const float4*)(Bp + (size_t)(k0 + 8) * ND);
        mma_slab(As, Bs, acc, wr, wc, lane);
        __syncthreads();
        stsT_tf32(As, a0, lk, lr); stsT_tf32(As, a1, lk, lr + 32);
        *(float4*)&Bs[bk][bn] = cvt4_tf32(b0);
        *(float4*)&Bs[bk + 8][bn] = cvt4_tf32(b1);
        __syncthreads();
    }
    mma_slab(As, Bs, acc, wr, wc, lane);

    float* P = g_part + (size_t)(b * KSPLIT + split) * NQ * ND;
#pragma unroll
    for (int mt = 0; mt < 2; mt++) {
#pragma unroll
        for (int nt = 0; nt < 4; nt++) {
            const int r0 = m0 + wr + mt * 16 + (lane >> 2);
            const int cn = n0 + wc + nt * 8 + 2 * (lane & 3);
            *(float2*)&P[(size_t)r0 * ND + cn] = make_float2(acc[mt][nt][0], acc[mt][nt][1]);
            *(float2*)&P[(size_t)(r0 + 8) * ND + cn] = make_float2(acc[mt][nt][2], acc[mt][nt][3]);
        }
    }
}

__global__ void __launch_bounds__(256) reduce_kernel(float* __restrict__ out,
                                                     const int* __restrict__ vlen) {
    const int i = blockIdx.x * 256 + threadIdx.x;   // float4 index, 131072 total
    const int b = i >> 15;
    const int off = i & 32767;
    const int nact = (vlen[b] + KCHUNK - 1) / KCHUNK;   // 1..KSPLIT active splits
    const float4* p = (const float4*)g_part;
    float4 s = p[(size_t)(b * KSPLIT + 0) * 32768 + off];
    for (int sp = 1; sp < nact; sp++) {
        const float4 t = p[(size_t)(b * KSPLIT + sp) * 32768 + off];
        s.x += t.x; s.y += t.y; s.z += t.z; s.w += t.w;
    }
    ((float4*)out)[i] = s;
}

// ---------------------------------------------------------------------------
extern "C" void kernel_launch(void* const* d_in, const int* in_sizes, int n_in,
                              void* d_out, int out_size) {
    const float* queries    = (const float*)d_in[0];
    const float* keys       = (const float*)d_in[1];
    const float* values     = (const float*)d_in[2];
    const int*   valid_lens = (const int*)d_in[3];
    const float* Wq         = (const float*)d_in[4];
    const float* Wk         = (const float*)d_in[5];
    const float* wv         = (const float*)d_in[6];
    float* out = (float*)d_out;

    (void)in_sizes; (void)n_in; (void)out_size;

    proj_gemm<<<64, 128>>>(queries, Wq, valid_lens, 0);    // 0: qproj
    proj_gemm<<<256, 128>>>(keys, Wk, valid_lens, 1);      // 1: kproj
    spacer_kernel<<<1, 32>>>();                            // 2: spacer (profiling alignment)
    scores_kernel<<<128, 512>>>(valid_lens, wv);           // 3: scores (capture target)
    av_gemm<<<dim3(ND / BN, NQ / BM, NB * KSPLIT), 128>>>(values, valid_lens);  // 4
    reduce_kernel<<<512, 256>>>(out, valid_lens);          // 5
}

// round 11
// speedup vs baseline: 1.2871x; 1.0981x over previous
#include <cuda_runtime.h>
#include <cuda_fp16.h>

// Problem constants
#define NB 4
#define NQ 256
#define NK 1024
#define ND 512
#define NH 256

// GEMM tiling
#define BM 64
#define BN 64
#define BK 16
#define KSPLIT 4
#define KCHUNK (NK / KSPLIT)   // 256

__device__ __align__(16) float  g_qproj[NB * NQ * NH];   // [bq][h]
__device__ __align__(16) __half g_kTh[NB * NH * NK];     // [b][h][k] fp16
__device__ __align__(16) float  g_attn[NB * NQ * NK];    // [bq][k]
__device__ __align__(16) float  g_part[NB * KSPLIT * NQ * ND];  // split-K partials
__device__ float g_spacer_sink[32];

__device__ __forceinline__ __half2 h2tanh_fast(__half2 a) {
    __half2 r;
    asm("tanh.approx.f16x2 %0, %1;"
        : "=r"(*reinterpret_cast<unsigned int*>(&r))
        : "r"(*reinterpret_cast<unsigned int*>(&a)));
    return r;
}

__device__ __forceinline__ float cvt_tf32(float x) {
    unsigned u;
    asm("cvt.rna.tf32.f32 %0, %1;" : "=r"(u) : "f"(x));
    return __uint_as_float(u);
}

__device__ __forceinline__ void mma_tf32(float c[4], const unsigned a[4],
                                         const unsigned b[2]) {
    asm volatile(
        "mma.sync.aligned.m16n8k8.row.col.f32.tf32.tf32.f32 "
        "{%0,%1,%2,%3}, {%4,%5,%6,%7}, {%8,%9}, {%0,%1,%2,%3};"
        : "+f"(c[0]), "+f"(c[1]), "+f"(c[2]), "+f"(c[3])
        : "r"(a[0]), "r"(a[1]), "r"(a[2]), "r"(a[3]), "r"(b[0]), "r"(b[1]));
}

// packed fp32x2 helpers (sm_103a)
__device__ __forceinline__ unsigned long long pack_f32x2(float lo, float hi) {
    unsigned long long r;
    asm("mov.b64 %0, {%1, %2};" : "=l"(r) : "f"(lo), "f"(hi));
    return r;
}
__device__ __forceinline__ void unpack_f32x2(unsigned long long v, float& lo, float& hi) {
    asm("mov.b64 {%0, %1}, %2;" : "=f"(lo), "=f"(hi) : "l"(v));
}
__device__ __forceinline__ unsigned long long add_f32x2(unsigned long long a,
                                                        unsigned long long b) {
    unsigned long long r;
    asm("add.rn.f32x2 %0, %1, %2;" : "=l"(r) : "l"(a), "l"(b));
    return r;
}

// ---------------------------------------------------------------------------
// smem helpers (k-major [BK][64+4])
// ---------------------------------------------------------------------------
__device__ __forceinline__ void stsT_tf32(float S[BK][BM + 4], float4 v, int lk, int row) {
    S[lk + 0][row] = cvt_tf32(v.x);
    S[lk + 1][row] = cvt_tf32(v.y);
    S[lk + 2][row] = cvt_tf32(v.z);
    S[lk + 3][row] = cvt_tf32(v.w);
}

__device__ __forceinline__ float4 cvt4_tf32(float4 v) {
    return make_float4(cvt_tf32(v.x), cvt_tf32(v.y), cvt_tf32(v.z), cvt_tf32(v.w));
}

// tf32 mma over one BK=16 slab; warp tile 32x32 (2 m16 x 4 n8 x 2 k8)
__device__ __forceinline__ void mma_slab(const float As[BK][BM + 4],
                                         const float Bs[BK][BN + 4],
                                         float acc[2][4][4], int wr, int wc, int lane) {
    const int qk = lane & 3, qr = lane >> 2;
#pragma unroll
    for (int ks = 0; ks < BK; ks += 8) {
        unsigned a[2][4], b[4][2];
#pragma unroll
        for (int mt = 0; mt < 2; mt++) {
            const int r = wr + mt * 16 + qr;
            a[mt][0] = __float_as_uint(As[ks + qk][r]);
            a[mt][1] = __float_as_uint(As[ks + qk][r + 8]);
            a[mt][2] = __float_as_uint(As[ks + 4 + qk][r]);
            a[mt][3] = __float_as_uint(As[ks + 4 + qk][r + 8]);
        }
#pragma unroll
        for (int nt = 0; nt < 4; nt++) {
            const int n = wc + nt * 8 + qr;
            b[nt][0] = __float_as_uint(Bs[ks + qk][n]);
            b[nt][1] = __float_as_uint(Bs[ks + 4 + qk][n]);
        }
#pragma unroll
        for (int mt = 0; mt < 2; mt++)
#pragma unroll
            for (int nt = 0; nt < 4; nt++)
                mma_tf32(acc[mt][nt], a[mt], b[nt]);
    }
}

// ---------------------------------------------------------------------------
// q/k projection (NT GEMMs) via tf32 tensor cores, one kernel, two launches.
// ---------------------------------------------------------------------------
__global__ void __launch_bounds__(128) proj_gemm(const float* __restrict__ Ain,
                                                 const float* __restrict__ Win,
                                                 const int* __restrict__ vlen,
                                                 int mode) {
    __shared__ __align__(16) float As[BK][BM + 4];
    __shared__ __align__(16) float Bs[BK][BN + 4];
    const int K = 512;
    const int bid = blockIdx.x, tid = threadIdx.x;

    const float *A, *B;
    int m0, n0;
    if (mode == 0) {
        m0 = (bid >> 2) * BM;  // 16 m-tiles over 1024 query rows
        n0 = (bid & 3) * BN;   // 4 n-tiles over 256 h
        A = Ain; B = Win;
    } else {
        m0 = (bid >> 6) * BM;  // 4 m-tiles over 256 h
        n0 = (bid & 63) * BN;  // 64 n-tiles over 4096 (b,k)
        if ((n0 & 1023) >= vlen[n0 >> 10]) return;   // dead k-tile
        A = Win; B = Ain;
    }

    const int lr = tid >> 2;
    const int lk = (tid & 3) << 2;
    const float* Ap = A + (size_t)(m0 + lr) * K + lk;
    const float* Bp = B + (size_t)(n0 + lr) * K + lk;

    float4 a0 = *(const float4*)Ap;
    float4 a1 = *(const float4*)(Ap + 32 * K);
    float4 b0 = *(const float4*)Bp;
    float4 b1 = *(const float4*)(Bp + 32 * K);
    stsT_tf32(As, a0, lk, lr); stsT_tf32(As, a1, lk, lr + 32);
    stsT_tf32(Bs, b0, lk, lr); stsT_tf32(Bs, b1, lk, lr + 32);
    __syncthreads();

    float acc[2][4][4] = {};
    const int lane = tid & 31, wid = tid >> 5;
    const int wr = (wid & 1) * 32, wc = (wid >> 1) * 32;

    for (int k0 = BK; k0 < K; k0 += BK) {
        a0 = *(const float4*)(Ap + k0);
        a1 = *(const float4*)(Ap + 32 * K + k0);
        b0 = *(const float4*)(Bp + k0);
        b1 = *(const float4*)(Bp + 32 * K + k0);
        mma_slab(As, Bs, acc, wr, wc, lane);
        __syncthreads();
        stsT_tf32(As, a0, lk, lr); stsT_tf32(As, a1, lk, lr + 32);
        stsT_tf32(Bs, b0, lk, lr); stsT_tf32(Bs, b1, lk, lr + 32);
        __syncthreads();
    }
    mma_slab(As, Bs, acc, wr, wc, lane);

#pragma unroll
    for (int mt = 0; mt < 2; mt++) {
#pragma unroll
        for (int nt = 0; nt < 4; nt++) {
            const int r0 = m0 + wr + mt * 16 + (lane >> 2);
            const int cn = wc + nt * 8 + 2 * (lane & 3);
            if (mode == 0) {
                *(float2*)&g_qproj[(size_t)r0 * NH + n0 + cn] =
                    make_float2(acc[mt][nt][0], acc[mt][nt][1]);
                *(float2*)&g_qproj[(size_t)(r0 + 8) * NH + n0 + cn] =
                    make_float2(acc[mt][nt][2], acc[mt][nt][3]);
            } else {
                const int gb = n0 >> 10;
                const int kx = (n0 & 1023) + cn;
                *(__half2*)&g_kTh[(size_t)(gb * NH + r0) * NK + kx] =
                    __floats2half2_rn(acc[mt][nt][0], acc[mt][nt][1]);
                *(__half2*)&g_kTh[(size_t)(gb * NH + r0 + 8) * NK + kx] =
                    __floats2half2_rn(acc[mt][nt][2], acc[mt][nt][3]);
            }
        }
    }
}

// Spacer: pushes scores_kernel to launch index 3 so ncu's capture lands on it.
__global__ void spacer_kernel() {
    if (threadIdx.x < 32) g_spacer_sink[threadIdx.x] = 1.0f;
}

// ---------------------------------------------------------------------------
// Scores + masked softmax. 256 blocks x 512 threads, 4 q-rows per block
// (2 co-resident blocks/SM -> 32 warps to hide LDG/MUFU latency).
// Hot loop: HFMA2 fp16 accumulation in 8-h chunks folded into packed f32.
// ---------------------------------------------------------------------------
__global__ void __launch_bounds__(512) scores_kernel(const int* __restrict__ vlen,
                                                     const float* __restrict__ wv) {
    __shared__ float qsT[NH][4];
    __shared__ __half2 qsh[NH][2];   // (r0,r1),(r2,r3) per h
    __shared__ __half2 wvh[NH];
    __shared__ float wred[16][4];
    __shared__ float bred[4];

    const int tid = threadIdx.x;
    const int b = blockIdx.x >> 6;          // 64 blocks per batch
    const int q0 = (blockIdx.x & 63) << 2;  // 4 q rows per block
    const int vl = vlen[b];
    const int kb2 = tid * 2;

    if (tid < NH) wvh[tid] = __float2half2_rn(wv[tid]);
#pragma unroll
    for (int i = 0; i < 2; i++) {
        const int idx = tid + i * 512;
        const int h = idx >> 2, r = idx & 3;
        qsT[h][r] = g_qproj[(size_t)(b * NQ + q0 + r) * NH + h];
    }
    __syncthreads();
    {
        const int h = tid >> 1, rp = tid & 1;
        qsh[h][rp] = __floats2half2_rn(qsT[h][2 * rp], qsT[h][2 * rp + 1]);
    }
    __syncthreads();

    // packed f32 accumulators: accf[rp][j] = (row 2rp, row 2rp+1) for key j
    unsigned long long accf[2][2] = {};
    if (kb2 < vl) {   // fully-masked threads skip all loads + tanh work (exact)
        const __half2* kp = (const __half2*)g_kTh + (size_t)b * NH * (NK / 2) + tid;
        const __half2 hz = __float2half2_rn(0.0f);
#pragma unroll 1
        for (int hc = 0; hc < NH; hc += 8) {
            __half2 acch[2][2];
#pragma unroll
            for (int rp = 0; rp < 2; rp++) { acch[rp][0] = hz; acch[rp][1] = hz; }
#pragma unroll
            for (int hh = 0; hh < 8; hh++) {
                const int h = hc + hh;
                const __half2 kv2 = kp[(size_t)h * (NK / 2)];   // keys 2t, 2t+1
                const __half2 k0 = __low2half2(kv2);
                const __half2 k1 = __high2half2(kv2);
                const __half2 w2 = wvh[h];
#pragma unroll
                for (int rp = 0; rp < 2; rp++) {
                    const __half2 q2 = qsh[h][rp];
                    acch[rp][0] = __hfma2(w2, h2tanh_fast(__hadd2(q2, k0)), acch[rp][0]);
                    acch[rp][1] = __hfma2(w2, h2tanh_fast(__hadd2(q2, k1)), acch[rp][1]);
                }
            }
            // fold fp16 chunk into packed f32 accumulators
#pragma unroll
            for (int rp = 0; rp < 2; rp++) {
                const float2 f0 = __half22float2(acch[rp][0]);
                const float2 f1 = __half22float2(acch[rp][1]);
                accf[rp][0] = add_f32x2(accf[rp][0], pack_f32x2(f0.x, f0.y));
                accf[rp][1] = add_f32x2(accf[rp][1], pack_f32x2(f1.x, f1.y));
            }
        }
    }

    float acc[4][2];
#pragma unroll
    for (int rp = 0; rp < 2; rp++) {
        unpack_f32x2(accf[rp][0], acc[2 * rp][0], acc[2 * rp + 1][0]);
        unpack_f32x2(accf[rp][1], acc[2 * rp][1], acc[2 * rp + 1][1]);
    }

    float s0[4], s1[4], rm[4];
#pragma unroll
    for (int r = 0; r < 4; r++) {
        s0[r] = (kb2 < vl) ? acc[r][0] : -1e6f;
        s1[r] = (kb2 + 1 < vl) ? acc[r][1] : -1e6f;
        rm[r] = fmaxf(s0[r], s1[r]);
    }
#pragma unroll
    for (int o = 16; o > 0; o >>= 1)
#pragma unroll
        for (int r = 0; r < 4; r++)
            rm[r] = fmaxf(rm[r], __shfl_xor_sync(0xffffffffu, rm[r], o));
    const int wid = tid >> 5, lane = tid & 31;
    if (lane == 0)
#pragma unroll
        for (int r = 0; r < 4; r++) wred[wid][r] = rm[r];
    __syncthreads();
    if (tid < 4) {
        float m = wred[0][tid];
#pragma unroll
        for (int w2 = 1; w2 < 16; w2++) m = fmaxf(m, wred[w2][tid]);
        bred[tid] = m;
    }
    __syncthreads();

    float e0[4], e1[4], rs[4];
#pragma unroll
    for (int r = 0; r < 4; r++) {
        const float mx = bred[r];
        e0[r] = __expf(s0[r] - mx);
        e1[r] = __expf(s1[r] - mx);
        rs[r] = e0[r] + e1[r];
    }
#pragma unroll
    for (int o = 16; o > 0; o >>= 1)
#pragma unroll
        for (int r = 0; r < 4; r++)
            rs[r] += __shfl_xor_sync(0xffffffffu, rs[r], o);
    if (lane == 0)
#pragma unroll
        for (int r = 0; r < 4; r++) wred[wid][r] = rs[r];
    __syncthreads();
    if (tid < 4) {
        float s = 0.0f;
#pragma unroll
        for (int w2 = 0; w2 < 16; w2++) s += wred[w2][tid];
        bred[tid] = 1.0f / s;
    }
    __syncthreads();

    // av only reads attn for k < ceil(vl/KCHUNK)*KCHUNK — skip dead stores
    const int klim = ((vl + KCHUNK - 1) / KCHUNK) * KCHUNK;
    if (kb2 < klim) {
#pragma unroll
        for (int r = 0; r < 4; r++) {
            const float inv = bred[r];
            float2 o2 = make_float2(e0[r] * inv, e1[r] * inv);
            *reinterpret_cast<float2*>(&g_attn[(size_t)(b * NQ + q0 + r) * NK + kb2]) = o2;
        }
    }
}

// ---------------------------------------------------------------------------
// Split-K attn @ values via tf32 tensor cores; partials to g_part.
// ---------------------------------------------------------------------------
__global__ void __launch_bounds__(128) av_gemm(const float* __restrict__ V,
                                               const int* __restrict__ vlen) {
    __shared__ __align__(16) float As[BK][BM + 4];
    __shared__ __align__(16) float Bs[BK][BN + 4];
    const int tid = threadIdx.x;
    const int b = blockIdx.z >> 2;
    const int split = blockIdx.z & 3;
    const int kbase = split * KCHUNK;
    if (kbase >= vlen[b]) return;   // partial is exactly zero; reduce skips it
    const int m0 = blockIdx.y * BM;
    const int n0 = blockIdx.x * BN;

    float acc[2][4][4] = {};
    const int lane = tid & 31, wid = tid >> 5;
    const int wr = (wid & 1) * 32, wc = (wid >> 1) * 32;

    const float* A = g_attn + (size_t)b * NQ * NK;
    const float* B = V + (size_t)b * NK * ND;

    const int lr = tid >> 2, lk = (tid & 3) << 2;   // A (transpose) loader
    const int bk = tid >> 4, bn = (tid & 15) << 2;  // B (direct) loader
    const float* Ap = A + (size_t)(m0 + lr) * NK + lk;
    const float* Bp = B + (size_t)bk * ND + n0 + bn;

    float4 a0 = *(const float4*)(Ap + kbase);
    float4 a1 = *(const float4*)(Ap + 32 * NK + kbase);
    float4 b0 = *(const float4*)(Bp + (size_t)kbase * ND);
    float4 b1 = *(const float4*)(Bp + (size_t)(kbase + 8) * ND);
    stsT_tf32(As, a0, lk, lr); stsT_tf32(As, a1, lk, lr + 32);
    *(float4*)&Bs[bk][bn] = cvt4_tf32(b0);
    *(float4*)&Bs[bk + 8][bn] = cvt4_tf32(b1);
    __syncthreads();

    for (int k0 = kbase + BK; k0 < kbase + KCHUNK; k0 += BK) {
        a0 = *(const float4*)(Ap + k0);
        a1 = *(const float4*)(Ap + 32 * NK + k0);
        b0 = *(const float4*)(Bp + (size_t)k0 * ND);
        b1 = *(const float4*)(Bp + (size_t)(k0 + 8) * ND);
        mma_slab(As, Bs, acc, wr, wc, lane);
        __syncthreads();
        stsT_tf32(As, a0, lk, lr); stsT_tf32(As, a1, lk, lr + 32);
        *(float4*)&Bs[bk][bn] = cvt4_tf32(b0);
        *(float4*)&Bs[bk + 8][bn] = cvt4_tf32(b1);
        __syncthreads();
    }
    mma_slab(As, Bs, acc, wr, wc, lane);

    float* P = g_part + (size_t)(b * KSPLIT + split) * NQ * ND;
#pragma unroll
    for (int mt = 0; mt < 2; mt++) {
#pragma unroll
        for (int nt = 0; nt < 4; nt++) {
            const int r0 = m0 + wr + mt * 16 + (lane >> 2);
            const int cn = n0 + wc + nt * 8 + 2 * (lane & 3);
            *(float2*)&P[(size_t)r0 * ND + cn] = make_float2(acc[mt][nt][0], acc[mt][nt][1]);
            *(float2*)&P[(size_t)(r0 + 8) * ND + cn] = make_float2(acc[mt][nt][2], acc[mt][nt][3]);
        }
    }
}

__global__ void __launch_bounds__(256) reduce_kernel(float* __restrict__ out,
                                                     const int* __restrict__ vlen) {
    const int i = blockIdx.x * 256 + threadIdx.x;   // float4 index, 131072 total
    const int b = i >> 15;
    const int off = i & 32767;
    const int nact = (vlen[b] + KCHUNK - 1) / KCHUNK;   // 1..KSPLIT active splits
    const float4* p = (const float4*)g_part;
    float4 s = p[(size_t)(b * KSPLIT + 0) * 32768 + off];
    for (int sp = 1; sp < nact; sp++) {
        const float4 t = p[(size_t)(b * KSPLIT + sp) * 32768 + off];
        s.x += t.x; s.y += t.y; s.z += t.z; s.w += t.w;
    }
    ((float4*)out)[i] = s;
}

// ---------------------------------------------------------------------------
extern "C" void kernel_launch(void* const* d_in, const int* in_sizes, int n_in,
                              void* d_out, int out_size) {
    const float* queries    = (const float*)d_in[0];
    const float* keys       = (const float*)d_in[1];
    const float* values     = (const float*)d_in[2];
    const int*   valid_lens = (const int*)d_in[3];
    const float* Wq         = (const float*)d_in[4];
    const float* Wk         = (const float*)d_in[5];
    const float* wv         = (const float*)d_in[6];
    float* out = (float*)d_out;

    (void)in_sizes; (void)n_in; (void)out_size;

    proj_gemm<<<64, 128>>>(queries, Wq, valid_lens, 0);    // 0: qproj
    proj_gemm<<<256, 128>>>(keys, Wk, valid_lens, 1);      // 1: kproj
    spacer_kernel<<<1, 32>>>();                            // 2: spacer (profiling alignment)
    scores_kernel<<<256, 512>>>(valid_lens, wv);           // 3: scores (capture target)
    av_gemm<<<dim3(ND / BN, NQ / BM, NB * KSPLIT), 128>>>(values, valid_lens);  // 4
    reduce_kernel<<<512, 256>>>(out, valid_lens);          // 5
}

// round 12
// speedup vs baseline: 1.4006x; 1.0882x over previous
#include <cuda_runtime.h>
#include <cuda_fp16.h>

// Problem constants
#define NB 4
#define NQ 256
#define NK 1024
#define ND 512
#define NH 256

// GEMM tiling
#define BM 64
#define BN 64
#define BK 16
#define KSPLIT 4
#define KCHUNK (NK / KSPLIT)   // 256

__device__ __align__(16) float  g_qproj[NB * NQ * NH];   // [bq][h]
__device__ __align__(16) __half g_kTh[NB * NH * NK];     // [b][h][k] fp16
__device__ __align__(16) float  g_attn[NB * NQ * NK];    // [bq][k]
__device__ __align__(16) float  g_part[NB * KSPLIT * NQ * ND];  // split-K partials
__device__ float g_spacer_sink[32];

__device__ __forceinline__ __half2 h2tanh_fast(__half2 a) {
    __half2 r;
    asm("tanh.approx.f16x2 %0, %1;"
        : "=r"(*reinterpret_cast<unsigned int*>(&r))
        : "r"(*reinterpret_cast<unsigned int*>(&a)));
    return r;
}

__device__ __forceinline__ float cvt_tf32(float x) {
    unsigned u;
    asm("cvt.rna.tf32.f32 %0, %1;" : "=r"(u) : "f"(x));
    return __uint_as_float(u);
}

__device__ __forceinline__ void mma_tf32(float c[4], const unsigned a[4],
                                         const unsigned b[2]) {
    asm volatile(
        "mma.sync.aligned.m16n8k8.row.col.f32.tf32.tf32.f32 "
        "{%0,%1,%2,%3}, {%4,%5,%6,%7}, {%8,%9}, {%0,%1,%2,%3};"
        : "+f"(c[0]), "+f"(c[1]), "+f"(c[2]), "+f"(c[3])
        : "r"(a[0]), "r"(a[1]), "r"(a[2]), "r"(a[3]), "r"(b[0]), "r"(b[1]));
}

// packed fp32x2 helpers (sm_103a)
__device__ __forceinline__ unsigned long long pack_f32x2(float lo, float hi) {
    unsigned long long r;
    asm("mov.b64 %0, {%1, %2};" : "=l"(r) : "f"(lo), "f"(hi));
    return r;
}
__device__ __forceinline__ void unpack_f32x2(unsigned long long v, float& lo, float& hi) {
    asm("mov.b64 {%0, %1}, %2;" : "=f"(lo), "=f"(hi) : "l"(v));
}
__device__ __forceinline__ unsigned long long add_f32x2(unsigned long long a,
                                                        unsigned long long b) {
    unsigned long long r;
    asm("add.rn.f32x2 %0, %1, %2;" : "=l"(r) : "l"(a), "l"(b));
    return r;
}

// ---------------------------------------------------------------------------
// smem helpers (k-major [BK][64+4])
// ---------------------------------------------------------------------------
__device__ __forceinline__ void stsT_tf32(float S[BK][BM + 4], float4 v, int lk, int row) {
    S[lk + 0][row] = cvt_tf32(v.x);
    S[lk + 1][row] = cvt_tf32(v.y);
    S[lk + 2][row] = cvt_tf32(v.z);
    S[lk + 3][row] = cvt_tf32(v.w);
}

__device__ __forceinline__ float4 cvt4_tf32(float4 v) {
    return make_float4(cvt_tf32(v.x), cvt_tf32(v.y), cvt_tf32(v.z), cvt_tf32(v.w));
}

// tf32 mma over one BK=16 slab; warp tile 32x32 (2 m16 x 4 n8 x 2 k8)
__device__ __forceinline__ void mma_slab(const float As[BK][BM + 4],
                                         const float Bs[BK][BN + 4],
                                         float acc[2][4][4], int wr, int wc, int lane) {
    const int qk = lane & 3, qr = lane >> 2;
#pragma unroll
    for (int ks = 0; ks < BK; ks += 8) {
        unsigned a[2][4], b[4][2];
#pragma unroll
        for (int mt = 0; mt < 2; mt++) {
            const int r = wr + mt * 16 + qr;
            a[mt][0] = __float_as_uint(As[ks + qk][r]);
            a[mt][1] = __float_as_uint(As[ks + qk][r + 8]);
            a[mt][2] = __float_as_uint(As[ks + 4 + qk][r]);
            a[mt][3] = __float_as_uint(As[ks + 4 + qk][r + 8]);
        }
#pragma unroll
        for (int nt = 0; nt < 4; nt++) {
            const int n = wc + nt * 8 + qr;
            b[nt][0] = __float_as_uint(Bs[ks + qk][n]);
            b[nt][1] = __float_as_uint(Bs[ks + 4 + qk][n]);
        }
#pragma unroll
        for (int mt = 0; mt < 2; mt++)
#pragma unroll
            for (int nt = 0; nt < 4; nt++)
                mma_tf32(acc[mt][nt], a[mt], b[nt]);
    }
}

// ---------------------------------------------------------------------------
// q/k projection (NT GEMMs) via tf32 tensor cores, one kernel, two launches.
// ---------------------------------------------------------------------------
__global__ void __launch_bounds__(128) proj_gemm(const float* __restrict__ Ain,
                                                 const float* __restrict__ Win,
                                                 const int* __restrict__ vlen,
                                                 int mode) {
    __shared__ __align__(16) float As[BK][BM + 4];
    __shared__ __align__(16) float Bs[BK][BN + 4];
    const int K = 512;
    const int bid = blockIdx.x, tid = threadIdx.x;

    const float *A, *B;
    int m0, n0;
    if (mode == 0) {
        m0 = (bid >> 2) * BM;  // 16 m-tiles over 1024 query rows
        n0 = (bid & 3) * BN;   // 4 n-tiles over 256 h
        A = Ain; B = Win;
    } else {
        m0 = (bid >> 6) * BM;  // 4 m-tiles over 256 h
        n0 = (bid & 63) * BN;  // 64 n-tiles over 4096 (b,k)
        if ((n0 & 1023) >= vlen[n0 >> 10]) return;   // dead k-tile
        A = Win; B = Ain;
    }

    const int lr = tid >> 2;
    const int lk = (tid & 3) << 2;
    const float* Ap = A + (size_t)(m0 + lr) * K + lk;
    const float* Bp = B + (size_t)(n0 + lr) * K + lk;

    float4 a0 = *(const float4*)Ap;
    float4 a1 = *(const float4*)(Ap + 32 * K);
    float4 b0 = *(const float4*)Bp;
    float4 b1 = *(const float4*)(Bp + 32 * K);
    stsT_tf32(As, a0, lk, lr); stsT_tf32(As, a1, lk, lr + 32);
    stsT_tf32(Bs, b0, lk, lr); stsT_tf32(Bs, b1, lk, lr + 32);
    __syncthreads();

    float acc[2][4][4] = {};
    const int lane = tid & 31, wid = tid >> 5;
    const int wr = (wid & 1) * 32, wc = (wid >> 1) * 32;

    for (int k0 = BK; k0 < K; k0 += BK) {
        a0 = *(const float4*)(Ap + k0);
        a1 = *(const float4*)(Ap + 32 * K + k0);
        b0 = *(const float4*)(Bp + k0);
        b1 = *(const float4*)(Bp + 32 * K + k0);
        mma_slab(As, Bs, acc, wr, wc, lane);
        __syncthreads();
        stsT_tf32(As, a0, lk, lr); stsT_tf32(As, a1, lk, lr + 32);
        stsT_tf32(Bs, b0, lk, lr); stsT_tf32(Bs, b1, lk, lr + 32);
        __syncthreads();
    }
    mma_slab(As, Bs, acc, wr, wc, lane);

#pragma unroll
    for (int mt = 0; mt < 2; mt++) {
#pragma unroll
        for (int nt = 0; nt < 4; nt++) {
            const int r0 = m0 + wr + mt * 16 + (lane >> 2);
            const int cn = wc + nt * 8 + 2 * (lane & 3);
            if (mode == 0) {
                *(float2*)&g_qproj[(size_t)r0 * NH + n0 + cn] =
                    make_float2(acc[mt][nt][0], acc[mt][nt][1]);
                *(float2*)&g_qproj[(size_t)(r0 + 8) * NH + n0 + cn] =
                    make_float2(acc[mt][nt][2], acc[mt][nt][3]);
            } else {
                const int gb = n0 >> 10;
                const int kx = (n0 & 1023) + cn;
                *(__half2*)&g_kTh[(size_t)(gb * NH + r0) * NK + kx] =
                    __floats2half2_rn(acc[mt][nt][0], acc[mt][nt][1]);
                *(__half2*)&g_kTh[(size_t)(gb * NH + r0 + 8) * NK + kx] =
                    __floats2half2_rn(acc[mt][nt][2], acc[mt][nt][3]);
            }
        }
    }
}

// Spacer: pushes scores_kernel to launch index 3 so ncu's capture lands on it.
__global__ void spacer_kernel() {
    if (threadIdx.x < 32) g_spacer_sink[threadIdx.x] = 1.0f;
}

// ---------------------------------------------------------------------------
// Scores + masked softmax. 512 blocks x 512 threads, 2 q-rows per block
// (up to 4 co-resident blocks/SM -> 64 warps to hide LDG/MUFU latency).
// Hot loop: HFMA2 fp16 accumulation in 8-h chunks folded into packed f32.
// ---------------------------------------------------------------------------
__global__ void __launch_bounds__(512) scores_kernel(const int* __restrict__ vlen,
                                                     const float* __restrict__ wv) {
    __shared__ float qsT[NH][2];
    __shared__ __half2 qsh[NH];      // (r0,r1) per h
    __shared__ __half2 wvh[NH];
    __shared__ float wred[16][2];
    __shared__ float bred[2];

    const int tid = threadIdx.x;
    const int b = blockIdx.x >> 7;           // 128 blocks per batch
    const int q0 = (blockIdx.x & 127) << 1;  // 2 q rows per block
    const int vl = vlen[b];
    const int kb2 = tid * 2;

    if (tid < NH) wvh[tid] = __float2half2_rn(wv[tid]);
    {
        const int h = tid >> 1, r = tid & 1;
        qsT[h][r] = g_qproj[(size_t)(b * NQ + q0 + r) * NH + h];
    }
    __syncthreads();
    if (tid < NH) qsh[tid] = __floats2half2_rn(qsT[tid][0], qsT[tid][1]);
    __syncthreads();

    // packed f32 accumulators: accf[j] = (row 0, row 1) for key j
    unsigned long long accf[2] = {};
    if (kb2 < vl) {   // fully-masked threads skip all loads + tanh work (exact)
        const __half2* kp = (const __half2*)g_kTh + (size_t)b * NH * (NK / 2) + tid;
        const __half2 hz = __float2half2_rn(0.0f);
#pragma unroll 1
        for (int hc = 0; hc < NH; hc += 8) {
            __half2 acch0 = hz, acch1 = hz;
#pragma unroll
            for (int hh = 0; hh < 8; hh++) {
                const int h = hc + hh;
                const __half2 kv2 = kp[(size_t)h * (NK / 2)];   // keys 2t, 2t+1
                const __half2 k0 = __low2half2(kv2);
                const __half2 k1 = __high2half2(kv2);
                const __half2 w2 = wvh[h];
                const __half2 q2 = qsh[h];
                acch0 = __hfma2(w2, h2tanh_fast(__hadd2(q2, k0)), acch0);
                acch1 = __hfma2(w2, h2tanh_fast(__hadd2(q2, k1)), acch1);
            }
            // fold fp16 chunk into packed f32 accumulators
            const float2 f0 = __half22float2(acch0);
            const float2 f1 = __half22float2(acch1);
            accf[0] = add_f32x2(accf[0], pack_f32x2(f0.x, f0.y));
            accf[1] = add_f32x2(accf[1], pack_f32x2(f1.x, f1.y));
        }
    }

    float acc[2][2];
    unpack_f32x2(accf[0], acc[0][0], acc[1][0]);
    unpack_f32x2(accf[1], acc[0][1], acc[1][1]);

    float s0[2], s1[2], rm[2];
#pragma unroll
    for (int r = 0; r < 2; r++) {
        s0[r] = (kb2 < vl) ? acc[r][0] : -1e6f;
        s1[r] = (kb2 + 1 < vl) ? acc[r][1] : -1e6f;
        rm[r] = fmaxf(s0[r], s1[r]);
    }
#pragma unroll
    for (int o = 16; o > 0; o >>= 1)
#pragma unroll
        for (int r = 0; r < 2; r++)
            rm[r] = fmaxf(rm[r], __shfl_xor_sync(0xffffffffu, rm[r], o));
    const int wid = tid >> 5, lane = tid & 31;
    if (lane == 0)
#pragma unroll
        for (int r = 0; r < 2; r++) wred[wid][r] = rm[r];
    __syncthreads();
    if (tid < 2) {
        float m = wred[0][tid];
#pragma unroll
        for (int w2 = 1; w2 < 16; w2++) m = fmaxf(m, wred[w2][tid]);
        bred[tid] = m;
    }
    __syncthreads();

    float e0[2], e1[2], rs[2];
#pragma unroll
    for (int r = 0; r < 2; r++) {
        const float mx = bred[r];
        e0[r] = __expf(s0[r] - mx);
        e1[r] = __expf(s1[r] - mx);
        rs[r] = e0[r] + e1[r];
    }
#pragma unroll
    for (int o = 16; o > 0; o >>= 1)
#pragma unroll
        for (int r = 0; r < 2; r++)
            rs[r] += __shfl_xor_sync(0xffffffffu, rs[r], o);
    if (lane == 0)
#pragma unroll
        for (int r = 0; r < 2; r++) wred[wid][r] = rs[r];
    __syncthreads();
    if (tid < 2) {
        float s = 0.0f;
#pragma unroll
        for (int w2 = 0; w2 < 16; w2++) s += wred[w2][tid];
        bred[tid] = 1.0f / s;
    }
    __syncthreads();

    // av only reads attn for k < ceil(vl/KCHUNK)*KCHUNK — skip dead stores
    const int klim = ((vl + KCHUNK - 1) / KCHUNK) * KCHUNK;
    if (kb2 < klim) {
#pragma unroll
        for (int r = 0; r < 2; r++) {
            const float inv = bred[r];
            float2 o2 = make_float2(e0[r] * inv, e1[r] * inv);
            *reinterpret_cast<float2*>(&g_attn[(size_t)(b * NQ + q0 + r) * NK + kb2]) = o2;
        }
    }
}

// ---------------------------------------------------------------------------
// Split-K attn @ values via tf32 tensor cores; partials to g_part.
// ---------------------------------------------------------------------------
__global__ void __launch_bounds__(128) av_gemm(const float* __restrict__ V,
                                               const int* __restrict__ vlen) {
    __shared__ __align__(16) float As[BK][BM + 4];
    __shared__ __align__(16) float Bs[BK][BN + 4];
    const int tid = threadIdx.x;
    const int b = blockIdx.z >> 2;
    const int split = blockIdx.z & 3;
    const int kbase = split * KCHUNK;
    if (kbase >= vlen[b]) return;   // partial is exactly zero; reduce skips it
    const int m0 = blockIdx.y * BM;
    const int n0 = blockIdx.x * BN;

    float acc[2][4][4] = {};
    const int lane = tid & 31, wid = tid >> 5;
    const int wr = (wid & 1) * 32, wc = (wid >> 1) * 32;

    const float* A = g_attn + (size_t)b * NQ * NK;
    const float* B = V + (size_t)b * NK * ND;

    const int lr = tid >> 2, lk = (tid & 3) << 2;   // A (transpose) loader
    const int bk = tid >> 4, bn = (tid & 15) << 2;  // B (direct) loader
    const float* Ap = A + (size_t)(m0 + lr) * NK + lk;
    const float* Bp = B + (size_t)bk * ND + n0 + bn;

    float4 a0 = *(const float4*)(Ap + kbase);
    float4 a1 = *(const float4*)(Ap + 32 * NK + kbase);
    float4 b0 = *(const float4*)(Bp + (size_t)kbase * ND);
    float4 b1 = *(const float4*)(Bp + (size_t)(kbase + 8) * ND);
    stsT_tf32(As, a0, lk, lr); stsT_tf32(As, a1, lk, lr + 32);
    *(float4*)&Bs[bk][bn] = cvt4_tf32(b0);
    *(float4*)&Bs[bk + 8][bn] = cvt4_tf32(b1);
    __syncthreads();

    for (int k0 = kbase + BK; k0 < kbase + KCHUNK; k0 += BK) {
        a0 = *(const float4*)(Ap + k0);
        a1 = *(const float4*)(Ap + 32 * NK + k0);
        b0 = *(const float4*)(Bp + (size_t)k0 * ND);
        b1 = *(const float4*)(Bp + (size_t)(k0 + 8) * ND);
        mma_slab(As, Bs, acc, wr, wc, lane);
        __syncthreads();
        stsT_tf32(As, a0, lk, lr); stsT_tf32(As, a1, lk, lr + 32);
        *(float4*)&Bs[bk][bn] = cvt4_tf32(b0);
        *(float4*)&Bs[bk + 8][bn] = cvt4_tf32(b1);
        __syncthreads();
    }
    mma_slab(As, Bs, acc, wr, wc, lane);

    float* P = g_part + (size_t)(b * KSPLIT + split) * NQ * ND;
#pragma unroll
    for (int mt = 0; mt < 2; mt++) {
#pragma unroll
        for (int nt = 0; nt < 4; nt++) {
            const int r0 = m0 + wr + mt * 16 + (lane >> 2);
            const int cn = n0 + wc + nt * 8 + 2 * (lane & 3);
            *(float2*)&P[(size_t)r0 * ND + cn] = make_float2(acc[mt][nt][0], acc[mt][nt][1]);
            *(float2*)&P[(size_t)(r0 + 8) * ND + cn] = make_float2(acc[mt][nt][2], acc[mt][nt][3]);
        }
    }
}

__global__ void __launch_bounds__(256) reduce_kernel(float* __restrict__ out,
                                                     const int* __restrict__ vlen) {
    const int i = blockIdx.x * 256 + threadIdx.x;   // float4 index, 131072 total
    const int b = i >> 15;
    const int off = i & 32767;
    const int nact = (vlen[b] + KCHUNK - 1) / KCHUNK;   // 1..KSPLIT active splits
    const float4* p = (const float4*)g_part;
    float4 s = p[(size_t)(b * KSPLIT + 0) * 32768 + off];
    for (int sp = 1; sp < nact; sp++) {
        const float4 t = p[(size_t)(b * KSPLIT + sp) * 32768 + off];
        s.x += t.x; s.y += t.y; s.z += t.z; s.w += t.w;
    }
    ((float4*)out)[i] = s;
}

// ---------------------------------------------------------------------------
extern "C" void kernel_launch(void* const* d_in, const int* in_sizes, int n_in,
                              void* d_out, int out_size) {
    const float* queries    = (const float*)d_in[0];
    const float* keys       = (const float*)d_in[1];
    const float* values     = (const float*)d_in[2];
    const int*   valid_lens = (const int*)d_in[3];
    const float* Wq         = (const float*)d_in[4];
    const float* Wk         = (const float*)d_in[5];
    const float* wv         = (const float*)d_in[6];
    float* out = (float*)d_out;

    (void)in_sizes; (void)n_in; (void)out_size;

    proj_gemm<<<64, 128>>>(queries, Wq, valid_lens, 0);    // 0: qproj
    proj_gemm<<<256, 128>>>(keys, Wk, valid_lens, 1);      // 1: kproj
    spacer_kernel<<<1, 32>>>();                            // 2: spacer (profiling alignment)
    scores_kernel<<<512, 512>>>(valid_lens, wv);           // 3: scores (capture target)
    av_gemm<<<dim3(ND / BN, NQ / BM, NB * KSPLIT), 128>>>(values, valid_lens);  // 4
    reduce_kernel<<<512, 256>>>(out, valid_lens);          // 5
}

// round 13
// speedup vs baseline: 1.7690x; 1.2630x over previous
#include <cuda_runtime.h>
#include <cuda_fp16.h>

// Problem constants
#define NB 4
#define NQ 256
#define NK 1024
#define ND 512
#define NH 256

// GEMM tiling
#define BM 64
#define BN 64
#define BK 16
#define KSPLIT 8
#define KCHUNK (NK / KSPLIT)   // 128

__device__ __align__(16) float  g_qproj[NB * NQ * NH];   // [bq][h]
__device__ __align__(16) __half g_kTh[NB * NH * NK];     // [b][h][k] fp16
__device__ __align__(16) float  g_attn[NB * NQ * NK];    // [bq][k]
__device__ __align__(16) float  g_part[NB * KSPLIT * NQ * ND];  // split-K partials
__device__ float g_spacer_sink[32];

__device__ __forceinline__ __half2 h2tanh_fast(__half2 a) {
    __half2 r;
    asm("tanh.approx.f16x2 %0, %1;"
        : "=r"(*reinterpret_cast<unsigned int*>(&r))
        : "r"(*reinterpret_cast<unsigned int*>(&a)));
    return r;
}

__device__ __forceinline__ float cvt_tf32(float x) {
    unsigned u;
    asm("cvt.rna.tf32.f32 %0, %1;" : "=r"(u) : "f"(x));
    return __uint_as_float(u);
}

__device__ __forceinline__ void mma_tf32(float c[4], const unsigned a[4],
                                         const unsigned b[2]) {
    asm volatile(
        "mma.sync.aligned.m16n8k8.row.col.f32.tf32.tf32.f32 "
        "{%0,%1,%2,%3}, {%4,%5,%6,%7}, {%8,%9}, {%0,%1,%2,%3};"
        : "+f"(c[0]), "+f"(c[1]), "+f"(c[2]), "+f"(c[3])
        : "r"(a[0]), "r"(a[1]), "r"(a[2]), "r"(a[3]), "r"(b[0]), "r"(b[1]));
}

// packed fp32x2 helpers (sm_103a)
__device__ __forceinline__ unsigned long long pack_f32x2(float lo, float hi) {
    unsigned long long r;
    asm("mov.b64 %0, {%1, %2};" : "=l"(r) : "f"(lo), "f"(hi));
    return r;
}
__device__ __forceinline__ void unpack_f32x2(unsigned long long v, float& lo, float& hi) {
    asm("mov.b64 {%0, %1}, %2;" : "=f"(lo), "=f"(hi) : "l"(v));
}
__device__ __forceinline__ unsigned long long add_f32x2(unsigned long long a,
                                                        unsigned long long b) {
    unsigned long long r;
    asm("add.rn.f32x2 %0, %1, %2;" : "=l"(r) : "l"(a), "l"(b));
    return r;
}

// ---------------------------------------------------------------------------
// smem helpers (k-major [BK][64+4])
// ---------------------------------------------------------------------------
__device__ __forceinline__ void stsT_tf32(float S[BK][BM + 4], float4 v, int lk, int row) {
    S[lk + 0][row] = cvt_tf32(v.x);
    S[lk + 1][row] = cvt_tf32(v.y);
    S[lk + 2][row] = cvt_tf32(v.z);
    S[lk + 3][row] = cvt_tf32(v.w);
}

__device__ __forceinline__ float4 cvt4_tf32(float4 v) {
    return make_float4(cvt_tf32(v.x), cvt_tf32(v.y), cvt_tf32(v.z), cvt_tf32(v.w));
}

// tf32 mma over one BK=16 slab; warp tile 32x32 (2 m16 x 4 n8 x 2 k8)
__device__ __forceinline__ void mma_slab(const float As[BK][BM + 4],
                                         const float Bs[BK][BN + 4],
                                         float acc[2][4][4], int wr, int wc, int lane) {
    const int qk = lane & 3, qr = lane >> 2;
#pragma unroll
    for (int ks = 0; ks < BK; ks += 8) {
        unsigned a[2][4], b[4][2];
#pragma unroll
        for (int mt = 0; mt < 2; mt++) {
            const int r = wr + mt * 16 + qr;
            a[mt][0] = __float_as_uint(As[ks + qk][r]);
            a[mt][1] = __float_as_uint(As[ks + qk][r + 8]);
            a[mt][2] = __float_as_uint(As[ks + 4 + qk][r]);
            a[mt][3] = __float_as_uint(As[ks + 4 + qk][r + 8]);
        }
#pragma unroll
        for (int nt = 0; nt < 4; nt++) {
            const int n = wc + nt * 8 + qr;
            b[nt][0] = __float_as_uint(Bs[ks + qk][n]);
            b[nt][1] = __float_as_uint(Bs[ks + 4 + qk][n]);
        }
#pragma unroll
        for (int mt = 0; mt < 2; mt++)
#pragma unroll
            for (int nt = 0; nt < 4; nt++)
                mma_tf32(acc[mt][nt], a[mt], b[nt]);
    }
}

// ---------------------------------------------------------------------------
// Fused q/k projection (NT GEMMs) via tf32 tensor cores (single launch).
//  bid <  64 : qproj  C[bq][h]     (fp32 out)
//  bid >= 64 : kproj  kTh[b][h][k] (fp16 out); dead k-tiles skipped
// ---------------------------------------------------------------------------
__global__ void __launch_bounds__(128) proj_gemm(const float* __restrict__ Qin,
                                                 const float* __restrict__ Kin,
                                                 const float* __restrict__ Wq,
                                                 const float* __restrict__ Wk,
                                                 const int* __restrict__ vlen) {
    __shared__ __align__(16) float As[BK][BM + 4];
    __shared__ __align__(16) float Bs[BK][BN + 4];
    const int K = 512;
    const int bid = blockIdx.x, tid = threadIdx.x;

    const float *A, *B;
    int m0, n0;
    const bool isq = bid < 64;
    if (isq) {
        m0 = (bid >> 2) * BM;  // 16 m-tiles over 1024 query rows
        n0 = (bid & 3) * BN;   // 4 n-tiles over 256 h
        A = Qin; B = Wq;
    } else {
        const int kb = bid - 64;
        m0 = (kb >> 6) * BM;   // 4 m-tiles over 256 h
        n0 = (kb & 63) * BN;   // 64 n-tiles over 4096 (b,k)
        if ((n0 & 1023) >= vlen[n0 >> 10]) return;   // dead k-tile
        A = Wk; B = Kin;
    }

    const int lr = tid >> 2;
    const int lk = (tid & 3) << 2;
    const float* Ap = A + (size_t)(m0 + lr) * K + lk;
    const float* Bp = B + (size_t)(n0 + lr) * K + lk;

    float4 a0 = *(const float4*)Ap;
    float4 a1 = *(const float4*)(Ap + 32 * K);
    float4 b0 = *(const float4*)Bp;
    float4 b1 = *(const float4*)(Bp + 32 * K);
    stsT_tf32(As, a0, lk, lr); stsT_tf32(As, a1, lk, lr + 32);
    stsT_tf32(Bs, b0, lk, lr); stsT_tf32(Bs, b1, lk, lr + 32);
    __syncthreads();

    float acc[2][4][4] = {};
    const int lane = tid & 31, wid = tid >> 5;
    const int wr = (wid & 1) * 32, wc = (wid >> 1) * 32;

    for (int k0 = BK; k0 < K; k0 += BK) {
        a0 = *(const float4*)(Ap + k0);
        a1 = *(const float4*)(Ap + 32 * K + k0);
        b0 = *(const float4*)(Bp + k0);
        b1 = *(const float4*)(Bp + 32 * K + k0);
        mma_slab(As, Bs, acc, wr, wc, lane);
        __syncthreads();
        stsT_tf32(As, a0, lk, lr); stsT_tf32(As, a1, lk, lr + 32);
        stsT_tf32(Bs, b0, lk, lr); stsT_tf32(Bs, b1, lk, lr + 32);
        __syncthreads();
    }
    mma_slab(As, Bs, acc, wr, wc, lane);

#pragma unroll
    for (int mt = 0; mt < 2; mt++) {
#pragma unroll
        for (int nt = 0; nt < 4; nt++) {
            const int r0 = m0 + wr + mt * 16 + (lane >> 2);
            const int cn = wc + nt * 8 + 2 * (lane & 3);
            if (isq) {
                *(float2*)&g_qproj[(size_t)r0 * NH + n0 + cn] =
                    make_float2(acc[mt][nt][0], acc[mt][nt][1]);
                *(float2*)&g_qproj[(size_t)(r0 + 8) * NH + n0 + cn] =
                    make_float2(acc[mt][nt][2], acc[mt][nt][3]);
            } else {
                const int gb = n0 >> 10;
                const int kx = (n0 & 1023) + cn;
                *(__half2*)&g_kTh[(size_t)(gb * NH + r0) * NK + kx] =
                    __floats2half2_rn(acc[mt][nt][0], acc[mt][nt][1]);
                *(__half2*)&g_kTh[(size_t)(gb * NH + r0 + 8) * NK + kx] =
                    __floats2half2_rn(acc[mt][nt][2], acc[mt][nt][3]);
            }
        }
    }
}

// Spacer: keeps the ncu capture (launch index 3) aligned on av_gemm.
__global__ void spacer_kernel() {
    if (threadIdx.x < 32) g_spacer_sink[threadIdx.x] = 1.0f;
}

// ---------------------------------------------------------------------------
// Scores + masked softmax. 512 blocks x 512 threads, 2 q-rows per block.
// (UNCHANGED from round 12's 36.9us version — near its MUFU floor.)
// ---------------------------------------------------------------------------
__global__ void __launch_bounds__(512) scores_kernel(const int* __restrict__ vlen,
                                                     const float* __restrict__ wv) {
    __shared__ float qsT[NH][2];
    __shared__ __half2 qsh[NH];      // (r0,r1) per h
    __shared__ __half2 wvh[NH];
    __shared__ float wred[16][2];
    __shared__ float bred[2];

    const int tid = threadIdx.x;
    const int b = blockIdx.x >> 7;           // 128 blocks per batch
    const int q0 = (blockIdx.x & 127) << 1;  // 2 q rows per block
    const int vl = vlen[b];
    const int kb2 = tid * 2;

    if (tid < NH) wvh[tid] = __float2half2_rn(wv[tid]);
    {
        const int h = tid >> 1, r = tid & 1;
        qsT[h][r] = g_qproj[(size_t)(b * NQ + q0 + r) * NH + h];
    }
    __syncthreads();
    if (tid < NH) qsh[tid] = __floats2half2_rn(qsT[tid][0], qsT[tid][1]);
    __syncthreads();

    unsigned long long accf[2] = {};
    if (kb2 < vl) {   // fully-masked threads skip all loads + tanh work (exact)
        const __half2* kp = (const __half2*)g_kTh + (size_t)b * NH * (NK / 2) + tid;
        const __half2 hz = __float2half2_rn(0.0f);
#pragma unroll 1
        for (int hc = 0; hc < NH; hc += 8) {
            __half2 acch0 = hz, acch1 = hz;
#pragma unroll
            for (int hh = 0; hh < 8; hh++) {
                const int h = hc + hh;
                const __half2 kv2 = kp[(size_t)h * (NK / 2)];   // keys 2t, 2t+1
                const __half2 k0 = __low2half2(kv2);
                const __half2 k1 = __high2half2(kv2);
                const __half2 w2 = wvh[h];
                const __half2 q2 = qsh[h];
                acch0 = __hfma2(w2, h2tanh_fast(__hadd2(q2, k0)), acch0);
                acch1 = __hfma2(w2, h2tanh_fast(__hadd2(q2, k1)), acch1);
            }
            const float2 f0 = __half22float2(acch0);
            const float2 f1 = __half22float2(acch1);
            accf[0] = add_f32x2(accf[0], pack_f32x2(f0.x, f0.y));
            accf[1] = add_f32x2(accf[1], pack_f32x2(f1.x, f1.y));
        }
    }

    float acc[2][2];
    unpack_f32x2(accf[0], acc[0][0], acc[1][0]);
    unpack_f32x2(accf[1], acc[0][1], acc[1][1]);

    float s0[2], s1[2], rm[2];
#pragma unroll
    for (int r = 0; r < 2; r++) {
        s0[r] = (kb2 < vl) ? acc[r][0] : -1e6f;
        s1[r] = (kb2 + 1 < vl) ? acc[r][1] : -1e6f;
        rm[r] = fmaxf(s0[r], s1[r]);
    }
#pragma unroll
    for (int o = 16; o > 0; o >>= 1)
#pragma unroll
        for (int r = 0; r < 2; r++)
            rm[r] = fmaxf(rm[r], __shfl_xor_sync(0xffffffffu, rm[r], o));
    const int wid = tid >> 5, lane = tid & 31;
    if (lane == 0)
#pragma unroll
        for (int r = 0; r < 2; r++) wred[wid][r] = rm[r];
    __syncthreads();
    if (tid < 2) {
        float m = wred[0][tid];
#pragma unroll
        for (int w2 = 1; w2 < 16; w2++) m = fmaxf(m, wred[w2][tid]);
        bred[tid] = m;
    }
    __syncthreads();

    float e0[2], e1[2], rs[2];
#pragma unroll
    for (int r = 0; r < 2; r++) {
        const float mx = bred[r];
        e0[r] = __expf(s0[r] - mx);
        e1[r] = __expf(s1[r] - mx);
        rs[r] = e0[r] + e1[r];
    }
#pragma unroll
    for (int o = 16; o > 0; o >>= 1)
#pragma unroll
        for (int r = 0; r < 2; r++)
            rs[r] += __shfl_xor_sync(0xffffffffu, rs[r], o);
    if (lane == 0)
#pragma unroll
        for (int r = 0; r < 2; r++) wred[wid][r] = rs[r];
    __syncthreads();
    if (tid < 2) {
        float s = 0.0f;
#pragma unroll
        for (int w2 = 0; w2 < 16; w2++) s += wred[w2][tid];
        bred[tid] = 1.0f / s;
    }
    __syncthreads();

    // av only reads attn for k < ceil(vl/KCHUNK)*KCHUNK — skip dead stores
    const int klim = ((vl + KCHUNK - 1) / KCHUNK) * KCHUNK;
    if (kb2 < klim) {
#pragma unroll
        for (int r = 0; r < 2; r++) {
            const float inv = bred[r];
            float2 o2 = make_float2(e0[r] * inv, e1[r] * inv);
            *reinterpret_cast<float2*>(&g_attn[(size_t)(b * NQ + q0 + r) * NK + kb2]) = o2;
        }
    }
}

// ---------------------------------------------------------------------------
// Split-K (x8) attn @ values via tf32 tensor cores; partials to g_part.
// ---------------------------------------------------------------------------
__global__ void __launch_bounds__(128) av_gemm(const float* __restrict__ V,
                                               const int* __restrict__ vlen) {
    __shared__ __align__(16) float As[BK][BM + 4];
    __shared__ __align__(16) float Bs[BK][BN + 4];
    const int tid = threadIdx.x;
    const int b = blockIdx.z >> 3;          // KSPLIT = 8
    const int split = blockIdx.z & 7;
    const int kbase = split * KCHUNK;
    if (kbase >= vlen[b]) return;   // partial is exactly zero; reduce skips it
    const int m0 = blockIdx.y * BM;
    const int n0 = blockIdx.x * BN;

    float acc[2][4][4] = {};
    const int lane = tid & 31, wid = tid >> 5;
    const int wr = (wid & 1) * 32, wc = (wid >> 1) * 32;

    const float* A = g_attn + (size_t)b * NQ * NK;
    const float* B = V + (size_t)b * NK * ND;

    const int lr = tid >> 2, lk = (tid & 3) << 2;   // A (transpose) loader
    const int bk = tid >> 4, bn = (tid & 15) << 2;  // B (direct) loader
    const float* Ap = A + (size_t)(m0 + lr) * NK + lk;
    const float* Bp = B + (size_t)bk * ND + n0 + bn;

    float4 a0 = *(const float4*)(Ap + kbase);
    float4 a1 = *(const float4*)(Ap + 32 * NK + kbase);
    float4 b0 = *(const float4*)(Bp + (size_t)kbase * ND);
    float4 b1 = *(const float4*)(Bp + (size_t)(kbase + 8) * ND);
    stsT_tf32(As, a0, lk, lr); stsT_tf32(As, a1, lk, lr + 32);
    *(float4*)&Bs[bk][bn] = cvt4_tf32(b0);
    *(float4*)&Bs[bk + 8][bn] = cvt4_tf32(b1);
    __syncthreads();

    for (int k0 = kbase + BK; k0 < kbase + KCHUNK; k0 += BK) {
        a0 = *(const float4*)(Ap + k0);
        a1 = *(const float4*)(Ap + 32 * NK + k0);
        b0 = *(const float4*)(Bp + (size_t)k0 * ND);
        b1 = *(const float4*)(Bp + (size_t)(k0 + 8) * ND);
        mma_slab(As, Bs, acc, wr, wc, lane);
        __syncthreads();
        stsT_tf32(As, a0, lk, lr); stsT_tf32(As, a1, lk, lr + 32);
        *(float4*)&Bs[bk][bn] = cvt4_tf32(b0);
        *(float4*)&Bs[bk + 8][bn] = cvt4_tf32(b1);
        __syncthreads();
    }
    mma_slab(As, Bs, acc, wr, wc, lane);

    float* P = g_part + (size_t)(b * KSPLIT + split) * NQ * ND;
#pragma unroll
    for (int mt = 0; mt < 2; mt++) {
#pragma unroll
        for (int nt = 0; nt < 4; nt++) {
            const int r0 = m0 + wr + mt * 16 + (lane >> 2);
            const int cn = n0 + wc + nt * 8 + 2 * (lane & 3);
            *(float2*)&P[(size_t)r0 * ND + cn] = make_float2(acc[mt][nt][0], acc[mt][nt][1]);
            *(float2*)&P[(size_t)(r0 + 8) * ND + cn] = make_float2(acc[mt][nt][2], acc[mt][nt][3]);
        }
    }
}

__global__ void __launch_bounds__(256) reduce_kernel(float* __restrict__ out,
                                                     const int* __restrict__ vlen) {
    const int i = blockIdx.x * 256 + threadIdx.x;   // float4 index, 131072 total
    const int b = i >> 15;
    const int off = i & 32767;
    const int nact = (vlen[b] + KCHUNK - 1) / KCHUNK;   // 1..KSPLIT active splits
    const float4* p = (const float4*)g_part;
    float4 s = p[(size_t)(b * KSPLIT + 0) * 32768 + off];
    for (int sp = 1; sp < nact; sp++) {
        const float4 t = p[(size_t)(b * KSPLIT + sp) * 32768 + off];
        s.x += t.x; s.y += t.y; s.z += t.z; s.w += t.w;
    }
    ((float4*)out)[i] = s;
}

// ---------------------------------------------------------------------------
extern "C" void kernel_launch(void* const* d_in, const int* in_sizes, int n_in,
                              void* d_out, int out_size) {
    const float* queries    = (const float*)d_in[0];
    const float* keys       = (const float*)d_in[1];
    const float* values     = (const float*)d_in[2];
    const int*   valid_lens = (const int*)d_in[3];
    const float* Wq         = (const float*)d_in[4];
    const float* Wk         = (const float*)d_in[5];
    const float* wv         = (const float*)d_in[6];
    float* out = (float*)d_out;

    (void)in_sizes; (void)n_in; (void)out_size;

    proj_gemm<<<320, 128>>>(queries, keys, Wq, Wk, valid_lens);  // 0: q+k proj
    scores_kernel<<<512, 512>>>(valid_lens, wv);                 // 1: scores
    spacer_kernel<<<1, 32>>>();                                  // 2: spacer
    av_gemm<<<dim3(ND / BN, NQ / BM, NB * KSPLIT), 128>>>(values, valid_lens);  // 3: av (capture)
    reduce_kernel<<<512, 256>>>(out, valid_lens);                // 4: reduce
}